// round 16
// baseline (speedup 1.0000x reference)
#include <cuda_runtime.h>
#include <cuda_fp16.h>
#include <cstdint>

// Problem constants
#define BATCH 1024
#define DIM   512
#define NCLS  50000
#define NSUB  3
#define NROWS (NCLS * NSUB)   // 150000
#define S_SCALE 50.0f
#define COS_M 0.8775825618903728f   // cos(0.5)
#define SIN_M 0.4794255386042030f   // sin(0.5)

// GEMM tiling: C[M=150000, N=1024] = Wn * En^T
#define MT 192                 // 64 classes per CTA tile
#define NTB 128                // batch cols per CTA
#define KC 64                  // K chunk (halves); 128B rows
#define NCHUNK (DIM / KC)      // 8
#define MTILES 782             // ceil(150000/192)
#define STAGES 3
#define A_STG_BYTES (MT * 128)    // 24576
#define B_STG_BYTES (NTB * 128)   // 16384
#define STG_BYTES   (A_STG_BYTES + B_STG_BYTES)  // 40960
#define SMEM_DYN    (STAGES * STG_BYTES)         // 122880
#define EPAD 130

// Throttled concurrent W-prep: 148 resident blocks, per-mtile counters
#define PREP_GRID 148
#define SPIN_LIMIT 50000       // x ~64ns ≈ 3.2ms bound, then full self-prep fallback

// Scratch (device globals: allocation-free contract)
__device__ __half g_eh[BATCH * DIM];
__device__ __half g_wh[(size_t)NROWS * DIM];
__device__ int g_labels[BATCH];
__device__ int g_cnt[MTILES];

// ---------------- PTX helpers (compute_103-safe: sm_80 feature set) ----------------
__device__ __forceinline__ uint32_t smem_u32(const void* p) {
    uint32_t a;
    asm("{ .reg .u64 t; cvta.to.shared.u64 t, %1; cvt.u32.u64 %0, t; }" : "=r"(a) : "l"(p));
    return a;
}

__device__ __forceinline__ void cp16(uint32_t s, const void* g) {
    asm volatile("cp.async.cg.shared.global [%0], [%1], 16;"
                 :: "r"(s), "l"((unsigned long long)__cvta_generic_to_global(g)));
}
#define CP_COMMIT() asm volatile("cp.async.commit_group;" ::: "memory")

__device__ __forceinline__ void ldsm4(uint32_t (&r)[4], uint32_t addr) {
    asm volatile("ldmatrix.sync.aligned.m8n8.x4.shared.b16 {%0,%1,%2,%3}, [%4];"
                 : "=r"(r[0]), "=r"(r[1]), "=r"(r[2]), "=r"(r[3]) : "r"(addr));
}

__device__ __forceinline__ void mma16816(float (&d)[4], const uint32_t (&a)[4],
                                         uint32_t b0, uint32_t b1) {
    asm volatile("mma.sync.aligned.m16n8k16.row.col.f32.f16.f16.f32 "
                 "{%0,%1,%2,%3}, {%4,%5,%6,%7}, {%8,%9}, {%0,%1,%2,%3};"
                 : "+f"(d[0]), "+f"(d[1]), "+f"(d[2]), "+f"(d[3])
                 : "r"(a[0]), "r"(a[1]), "r"(a[2]), "r"(a[3]), "r"(b0), "r"(b1));
}

// Normalize one row (warp-collective) from fp32 src into fp16 dst.
__device__ __forceinline__ void norm_row_warp(const float* __restrict__ src,
                                              __half* __restrict__ dst,
                                              int row, int lane) {
    const float4* rp = (const float4*)(src + (size_t)row * DIM);
    float4 v[4];
    float ss = 0.f;
#pragma unroll
    for (int i = 0; i < 4; i++) {
        v[i] = rp[i * 32 + lane];
        ss += v[i].x * v[i].x + v[i].y * v[i].y + v[i].z * v[i].z + v[i].w * v[i].w;
    }
#pragma unroll
    for (int o = 16; o; o >>= 1) ss += __shfl_xor_sync(0xffffffffu, ss, o);

    float inv = 1.0f / fmaxf(sqrtf(ss), 1e-12f);

    uint2* dp = (uint2*)dst + (size_t)row * 128;
#pragma unroll
    for (int i = 0; i < 4; i++) {
        __half2 p0 = __floats2half2_rn(v[i].x * inv, v[i].y * inv);
        __half2 p1 = __floats2half2_rn(v[i].z * inv, v[i].w * inv);
        uint2 pk;
        pk.x = *(uint32_t*)&p0;
        pk.y = *(uint32_t*)&p1;
        dp[i * 32 + lane] = pk;
    }
}

// ---------------- E normalize + labels + counter reset (origin stream, first) ----------------
__global__ void norm_e_label_kernel(const float* __restrict__ src, const void* __restrict__ lab) {
    const int tid = threadIdx.x;

    if (blockIdx.x == 0) {
        __shared__ int not64;
        if (tid == 0) not64 = 0;
#pragma unroll
        for (int j = 0; j < 4; j++) {               // reset per-replay mtile counters
            int i = tid + j * 256;
            if (i < MTILES) g_cnt[i] = 0;
        }
        __syncthreads();
        if (tid < 256) {
#pragma unroll
            for (int j = 0; j < 2; j++) {
                long long v = ((const long long*)lab)[tid * 2 + j];  // first 4KB: safe either way
                if (v < 0 || v >= NCLS) not64 = 1;                   // idempotent store
            }
        }
        __syncthreads();
#pragma unroll
        for (int j = 0; j < 4; j++) {
            int i = tid + j * 256;
            if (not64) g_labels[i] = ((const int*)lab)[i];
            else       g_labels[i] = (int)((const long long*)lab)[i];
        }
    }

    int row = blockIdx.x * 8 + (tid >> 5);   // 128 blocks x 8 warps = 1024 rows
    norm_row_warp(src, g_eh, row, tid & 31);
}

// ---------------- Throttled W prep: 148 blocks, mtile-major, publishes per-mtile ----------------
__global__ void norm_w_kernel(const float* __restrict__ src) {
    const int tid  = threadIdx.x;
    const int wid  = tid >> 5;
    const int lane = tid & 31;

    for (int m = blockIdx.x; m < MTILES; m += PREP_GRID) {
        const int row0 = m * MT;
#pragma unroll 1
        for (int i = 0; i < 3; i++) {               // 8 warps x 3 passes x 8 rows = 192 rows
            int row = row0 + wid + i * 64 + 0;      // interleave warps across rows
            row = row0 + (i * 8 + wid) * 8 + 0;     // contiguous 8-row groups per (i,wid)
#pragma unroll 1
            for (int r = 0; r < 8; r++) {
                int rr = row0 + (i * 8 + wid) * 8 + r;
                if (rr < NROWS) norm_row_warp(src, g_wh, rr, lane);
            }
        }
        __syncthreads();
        __threadfence();                            // release rows before publish
        if (tid == 0) atomicAdd(&g_cnt[m], 1);
    }
}

// ---------------- GEMM + max3/arcface epilogue (HMMA mma.sync, fp32 acc) ----------------
// Swizzled smem layout: byte = r*128 + ((c ^ (r&7)) << 4),  c = 16B-column (0..7)

__device__ __forceinline__ void load_stage(uint32_t st, int mrow0, int n0, int k0, int tid) {
    // A (W): 192 rows x 64 halves = 1536 x 16B units, 6/thread @256
#pragma unroll
    for (int j = 0; j < 6; j++) {
        int u = tid + j * 256;
        int r = u >> 3, cu = u & 7;
        int gr = mrow0 + r; gr = gr < NROWS ? gr : NROWS - 1;
        const __half* gp = g_wh + (size_t)gr * DIM + k0 + cu * 8;
        cp16(st + r * 128 + ((cu ^ (r & 7)) << 4), gp);
    }
    // B (E): 128 rows x 64 halves = 1024 units, 4/thread @256
#pragma unroll
    for (int j = 0; j < 4; j++) {
        int u = tid + j * 256;
        int r = u >> 3, cu = u & 7;
        const __half* gp = g_eh + (size_t)(n0 + r) * DIM + k0 + cu * 8;
        cp16(st + A_STG_BYTES + r * 128 + ((cu ^ (r & 7)) << 4), gp);
    }
}

__global__ __launch_bounds__(256, 1)
void arcface_gemm_kernel(const float* __restrict__ wt_raw, float* __restrict__ out) {
    extern __shared__ __align__(128) char smem_raw[];
    const uint32_t sbase = smem_u32(smem_raw);

    const int tid  = threadIdx.x;
    const int wid  = tid >> 5;
    const int lane = tid & 31;
    const int ntile = blockIdx.x;        // 0..7 (fastest: share W panel in L2)
    const int mtile = blockIdx.y;        // 0..781
    const int mrow0 = mtile * MT;
    const int n0    = ntile * NTB;

    // Bounded wait for this mtile's W rows; full self-prep fallback (hang-proof, R14-proven).
    __shared__ int s_ready;
    if (tid == 0) {
        volatile int* cp = (volatile int*)&g_cnt[mtile];
        int it = 0, ok = 0;
        while (it++ < SPIN_LIMIT) {
            if (*cp >= 1) { ok = 1; break; }
            __nanosleep(64);
        }
        __threadfence();                 // acquire
        s_ready = ok;
    }
    __syncthreads();
    if (!s_ready) {
#pragma unroll 1
        for (int i = 0; i < 24; i++) {
            int row = mrow0 + wid * 24 + i;
            if (row < NROWS) norm_row_warp(wt_raw, g_wh, row, lane);
        }
        __threadfence();
        __syncthreads();
    }

    // warp tile: 48(M) x 64(N); warp grid 4(M) x 2(N)
    const int wm0 = (wid & 3) * 48;
    const int wn0 = (wid >> 2) * 64;

    int ra[3], xa[3];
#pragma unroll
    for (int i = 0; i < 3; i++) {
        int m = wm0 + 16 * i + (lane & 15);
        ra[i] = m * 128;
        xa[i] = m & 7;
    }
    const int selA = lane >> 4;
    int rb[4], xb[4];
#pragma unroll
    for (int g = 0; g < 4; g++) {
        int n = wn0 + 16 * g + ((lane >> 4) << 3) + (lane & 7);
        rb[g] = n * 128;
        xb[g] = n & 7;
    }
    const int selB = (lane >> 3) & 1;

    float acc[3][8][4];
#pragma unroll
    for (int i = 0; i < 3; i++)
#pragma unroll
        for (int g = 0; g < 8; g++)
#pragma unroll
            for (int q = 0; q < 4; q++) acc[i][g][q] = 0.f;

    // prologue: issue chunks 0,1
    load_stage(sbase + 0 * STG_BYTES, mrow0, n0, 0 * KC, tid); CP_COMMIT();
    load_stage(sbase + 1 * STG_BYTES, mrow0, n0, 1 * KC, tid); CP_COMMIT();

    for (int s = 0; s < NCHUNK; s++) {
        if (s < NCHUNK - 2) asm volatile("cp.async.wait_group 1;" ::: "memory");
        else                asm volatile("cp.async.wait_group 0;" ::: "memory");
        __syncthreads();

        if (s + 2 < NCHUNK) {
            load_stage(sbase + ((s + 2) % STAGES) * STG_BYTES, mrow0, n0, (s + 2) * KC, tid);
            CP_COMMIT();
        }

        const uint32_t ab = sbase + (s % STAGES) * STG_BYTES;
        const uint32_t bb = ab + A_STG_BYTES;
#pragma unroll
        for (int kk = 0; kk < 4; kk++) {
            uint32_t a[3][4];
            const int ca = kk * 2 + selA;
#pragma unroll
            for (int i = 0; i < 3; i++)
                ldsm4(a[i], ab + ra[i] + ((ca ^ xa[i]) << 4));

            uint32_t b[8][2];
            const int cb = kk * 2 + selB;
#pragma unroll
            for (int g = 0; g < 4; g++) {
                uint32_t r4[4];
                ldsm4(r4, bb + rb[g] + ((cb ^ xb[g]) << 4));
                b[2 * g][0] = r4[0]; b[2 * g][1] = r4[1];
                b[2 * g + 1][0] = r4[2]; b[2 * g + 1][1] = r4[3];
            }
#pragma unroll
            for (int i = 0; i < 3; i++)
#pragma unroll
                for (int g = 0; g < 8; g++)
                    mma16816(acc[i][g], a[i], b[g][0], b[g][1]);
        }
        __syncthreads();
    }

    // -------- epilogue: accum -> SMEM [192][130], then max3 + arcface + store --------
    float* ep = (float*)smem_raw;
#pragma unroll
    for (int i = 0; i < 3; i++) {
        int row = wm0 + 16 * i + (lane >> 2);
#pragma unroll
        for (int g = 0; g < 8; g++) {
            int col = wn0 + 8 * g + 2 * (lane & 3);
            *(float2*)&ep[row * EPAD + col]       = make_float2(acc[i][g][0], acc[i][g][1]);
            *(float2*)&ep[(row + 8) * EPAD + col] = make_float2(acc[i][g][2], acc[i][g][3]);
        }
    }
    __syncthreads();

    const int cls  = tid & 63;           // local class; lanes consecutive -> coalesced
    const int bg   = tid >> 6;           // 0..3
    const int clsG = mtile * 64 + cls;
    if (clsG < NCLS) {
        const int r3 = 3 * cls;
#pragma unroll 4
        for (int i = 0; i < 32; i++) {
            int b = bg * 32 + i;
            float v0 = ep[r3 * EPAD + b];
            float v1 = ep[(r3 + 1) * EPAD + b];
            float v2 = ep[(r3 + 2) * EPAD + b];
            float m = fmaxf(v0, fmaxf(v1, v2));
            float v = m;
            if (g_labels[n0 + b] == clsG) {
                float mc = fminf(fmaxf(m, -1.0f + 1e-7f), 1.0f - 1e-7f);
                v = mc * COS_M - sqrtf(fmaxf(1.0f - mc * mc, 0.0f)) * SIN_M;
            }
            out[(size_t)(n0 + b) * NCLS + clsG] = S_SCALE * v;
        }
    }
}

// ---------------- Launch: throttled prep on origin, GEMM concurrent on forked stream ----------------
extern "C" void kernel_launch(void* const* d_in, const int* in_sizes, int n_in,
                              void* d_out, int out_size) {
    (void)in_sizes; (void)n_in; (void)out_size;
    const float* emb = (const float*)d_in[0];
    const void*  lab = d_in[1];
    const float* wt  = (const float*)d_in[2];
    float* out = (float*)d_out;

    static cudaStream_t s1 = nullptr;
    static cudaEvent_t ev0 = nullptr, ev1 = nullptr;
    if (!s1) {
        cudaStreamCreateWithFlags(&s1, cudaStreamNonBlocking);
        cudaEventCreateWithFlags(&ev0, cudaEventDisableTiming);
        cudaEventCreateWithFlags(&ev1, cudaEventDisableTiming);
        cudaFuncSetAttribute(arcface_gemm_kernel,
                             cudaFuncAttributeMaxDynamicSharedMemorySize, SMEM_DYN);
    }

    // Origin: counters + labels + E-norm (GEMM prerequisites except W).
    norm_e_label_kernel<<<BATCH / 8, 256>>>(emb, lab);

    // Fork s1 after prerequisites.
    cudaEventRecord(ev0, 0);
    cudaStreamWaitEvent(s1, ev0, 0);

    // Origin: throttled W prep — 148 co-resident blocks, ~2-3 TB/s, hidden under GEMM.
    norm_w_kernel<<<PREP_GRID, 256>>>(wt);

    // s1: monolithic GEMM; per-mtile bounded wait with self-prep fallback.
    dim3 grid(BATCH / NTB, MTILES);   // (8, 782), ntile fastest
    arcface_gemm_kernel<<<grid, 256, SMEM_DYN, s1>>>(wt, out);

    // Join back to origin so the graph's leaf includes the GEMM.
    cudaEventRecord(ev1, s1);
    cudaStreamWaitEvent(0, ev1, 0);
}

// round 17
// speedup vs baseline: 1.1661x; 1.1661x over previous
#include <cuda_runtime.h>
#include <cuda_fp16.h>
#include <cstdint>

// Problem constants
#define BATCH 1024
#define DIM   512
#define NCLS  50000
#define NSUB  3
#define NROWS (NCLS * NSUB)   // 150000
#define S_SCALE 50.0f
#define COS_M 0.8775825618903728f   // cos(0.5)
#define SIN_M 0.4794255386042030f   // sin(0.5)

// GEMM tiling: C[M=150000, N=1024] = Wn * En^T
#define MT 192                 // 64 classes per CTA tile
#define NTB 128                // batch cols per CTA
#define KC 64                  // K chunk (halves); 128B rows
#define NCHUNK (DIM / KC)      // 8
#define MTILES 782             // ceil(150000/192)
#define STAGES 3
#define A_STG_BYTES (MT * 128)    // 24576
#define B_STG_BYTES (NTB * 128)   // 16384
#define STG_BYTES   (A_STG_BYTES + B_STG_BYTES)  // 40960
#define SMEM_DYN    (STAGES * STG_BYTES)         // 122880
#define EPAD 130

// Unified prep grid: W blocks then E blocks
#define W_BLOCKS 18750         // 8 rows/block
#define E_BLOCKS 128
#define PREP_BLOCKS (W_BLOCKS + E_BLOCKS)

// Scratch (device globals: allocation-free contract)
__device__ __half g_eh[BATCH * DIM];
__device__ __half g_wh[(size_t)NROWS * DIM];
__device__ int g_labels[BATCH];

// ---------------- PTX helpers (compute_103-safe: sm_80 feature set) ----------------
__device__ __forceinline__ uint32_t smem_u32(const void* p) {
    uint32_t a;
    asm("{ .reg .u64 t; cvta.to.shared.u64 t, %1; cvt.u32.u64 %0, t; }" : "=r"(a) : "l"(p));
    return a;
}

__device__ __forceinline__ void cp16(uint32_t s, const void* g) {
    asm volatile("cp.async.cg.shared.global [%0], [%1], 16;"
                 :: "r"(s), "l"((unsigned long long)__cvta_generic_to_global(g)));
}
#define CP_COMMIT() asm volatile("cp.async.commit_group;" ::: "memory")

__device__ __forceinline__ void ldsm4(uint32_t (&r)[4], uint32_t addr) {
    asm volatile("ldmatrix.sync.aligned.m8n8.x4.shared.b16 {%0,%1,%2,%3}, [%4];"
                 : "=r"(r[0]), "=r"(r[1]), "=r"(r[2]), "=r"(r[3]) : "r"(addr));
}

__device__ __forceinline__ void mma16816(float (&d)[4], const uint32_t (&a)[4],
                                         uint32_t b0, uint32_t b1) {
    asm volatile("mma.sync.aligned.m16n8k16.row.col.f32.f16.f16.f32 "
                 "{%0,%1,%2,%3}, {%4,%5,%6,%7}, {%8,%9}, {%0,%1,%2,%3};"
                 : "+f"(d[0]), "+f"(d[1]), "+f"(d[2]), "+f"(d[3])
                 : "r"(a[0]), "r"(a[1]), "r"(a[2]), "r"(a[3]), "r"(b0), "r"(b1));
}

// Normalize one row (warp-collective) from fp32 src into fp16 dst.
__device__ __forceinline__ void norm_row_warp(const float* __restrict__ src,
                                              __half* __restrict__ dst,
                                              int row, int lane) {
    const float4* rp = (const float4*)(src + (size_t)row * DIM);
    float4 v[4];
    float ss = 0.f;
#pragma unroll
    for (int i = 0; i < 4; i++) {
        v[i] = rp[i * 32 + lane];
        ss += v[i].x * v[i].x + v[i].y * v[i].y + v[i].z * v[i].z + v[i].w * v[i].w;
    }
#pragma unroll
    for (int o = 16; o; o >>= 1) ss += __shfl_xor_sync(0xffffffffu, ss, o);

    float inv = 1.0f / fmaxf(sqrtf(ss), 1e-12f);

    uint2* dp = (uint2*)dst + (size_t)row * 128;
#pragma unroll
    for (int i = 0; i < 4; i++) {
        __half2 p0 = __floats2half2_rn(v[i].x * inv, v[i].y * inv);
        __half2 p1 = __floats2half2_rn(v[i].z * inv, v[i].w * inv);
        uint2 pk;
        pk.x = *(uint32_t*)&p0;
        pk.y = *(uint32_t*)&p1;
        dp[i * 32 + lane] = pk;
    }
}

// ---------------- Unified prep: W-norm + E-norm + labels in ONE launch ----------------
__global__ void prep_kernel(const float* __restrict__ wt, const float* __restrict__ emb,
                            const void* __restrict__ lab) {
    const int tid  = threadIdx.x;
    const int lane = tid & 31;
    const int bid  = blockIdx.x;

    if (bid < W_BLOCKS) {
        int row = bid * 8 + (tid >> 5);
        if (row < NROWS) norm_row_warp(wt, g_wh, row, lane);
        return;
    }

    const int eb = bid - W_BLOCKS;        // 0..127
    if (eb == 0) {
        __shared__ int not64;
        if (tid == 0) not64 = 0;
        __syncthreads();
        if (tid < 256) {
#pragma unroll
            for (int j = 0; j < 2; j++) {
                long long v = ((const long long*)lab)[tid * 2 + j];  // first 4KB: safe either way
                if (v < 0 || v >= NCLS) not64 = 1;                   // idempotent store
            }
        }
        __syncthreads();
#pragma unroll
        for (int j = 0; j < 4; j++) {
            int i = tid + j * 256;
            if (not64) g_labels[i] = ((const int*)lab)[i];
            else       g_labels[i] = (int)((const long long*)lab)[i];
        }
    }
    int row = eb * 8 + (tid >> 5);        // 128 blocks x 8 warps = 1024 rows
    norm_row_warp(emb, g_eh, row, lane);
}

// ---------------- GEMM + max/arcface epilogue (HMMA mma.sync, fp32 acc) ----------------
// Swizzled smem layout: byte = r*128 + ((c ^ (r&7)) << 4),  c = 16B-column (0..7)

__device__ __forceinline__ void load_stage(uint32_t st, int mrow0, int n0, int k0, int tid) {
    // A (W): 192 rows x 64 halves = 1536 x 16B units, 6/thread @256
#pragma unroll
    for (int j = 0; j < 6; j++) {
        int u = tid + j * 256;
        int r = u >> 3, cu = u & 7;
        int gr = mrow0 + r; gr = gr < NROWS ? gr : NROWS - 1;
        const __half* gp = g_wh + (size_t)gr * DIM + k0 + cu * 8;
        cp16(st + r * 128 + ((cu ^ (r & 7)) << 4), gp);
    }
    // B (E): 128 rows x 64 halves = 1024 units, 4/thread @256
#pragma unroll
    for (int j = 0; j < 4; j++) {
        int u = tid + j * 256;
        int r = u >> 3, cu = u & 7;
        const __half* gp = g_eh + (size_t)(n0 + r) * DIM + k0 + cu * 8;
        cp16(st + A_STG_BYTES + r * 128 + ((cu ^ (r & 7)) << 4), gp);
    }
}

__global__ __launch_bounds__(256, 1)
void arcface_gemm_kernel(float* __restrict__ out) {
    extern __shared__ __align__(128) char smem_raw[];
    const uint32_t sbase = smem_u32(smem_raw);

    const int tid  = threadIdx.x;
    const int wid  = tid >> 5;
    const int lane = tid & 31;
    const int ntile = blockIdx.x;        // 0..7 (fastest: share W panel in L2)
    const int mtile = blockIdx.y;        // 0..781
    const int mrow0 = mtile * MT;
    const int n0    = ntile * NTB;

    // warp tile: 48(M) x 64(N); warp grid 4(M) x 2(N)
    const int wm0 = (wid & 3) * 48;
    const int wn0 = (wid >> 2) * 64;

    int ra[3], xa[3];
#pragma unroll
    for (int i = 0; i < 3; i++) {
        int m = wm0 + 16 * i + (lane & 15);
        ra[i] = m * 128;
        xa[i] = m & 7;
    }
    const int selA = lane >> 4;
    int rb[4], xb[4];
#pragma unroll
    for (int g = 0; g < 4; g++) {
        int n = wn0 + 16 * g + ((lane >> 4) << 3) + (lane & 7);
        rb[g] = n * 128;
        xb[g] = n & 7;
    }
    const int selB = (lane >> 3) & 1;

    float acc[3][8][4];
#pragma unroll
    for (int i = 0; i < 3; i++)
#pragma unroll
        for (int g = 0; g < 8; g++)
#pragma unroll
            for (int q = 0; q < 4; q++) acc[i][g][q] = 0.f;

    // prologue: issue chunks 0,1
    load_stage(sbase + 0 * STG_BYTES, mrow0, n0, 0 * KC, tid); CP_COMMIT();
    load_stage(sbase + 1 * STG_BYTES, mrow0, n0, 1 * KC, tid); CP_COMMIT();

    for (int s = 0; s < NCHUNK; s++) {
        if (s < NCHUNK - 2) asm volatile("cp.async.wait_group 1;" ::: "memory");
        else                asm volatile("cp.async.wait_group 0;" ::: "memory");
        __syncthreads();

        if (s + 2 < NCHUNK) {
            load_stage(sbase + ((s + 2) % STAGES) * STG_BYTES, mrow0, n0, (s + 2) * KC, tid);
            CP_COMMIT();
        }

        const uint32_t ab = sbase + (s % STAGES) * STG_BYTES;
        const uint32_t bb = ab + A_STG_BYTES;
#pragma unroll
        for (int kk = 0; kk < 4; kk++) {
            uint32_t a[3][4];
            const int ca = kk * 2 + selA;
#pragma unroll
            for (int i = 0; i < 3; i++)
                ldsm4(a[i], ab + ra[i] + ((ca ^ xa[i]) << 4));

            uint32_t b[8][2];
            const int cb = kk * 2 + selB;
#pragma unroll
            for (int g = 0; g < 4; g++) {
                uint32_t r4[4];
                ldsm4(r4, bb + rb[g] + ((cb ^ xb[g]) << 4));
                b[2 * g][0] = r4[0]; b[2 * g][1] = r4[1];
                b[2 * g + 1][0] = r4[2]; b[2 * g + 1][1] = r4[3];
            }
#pragma unroll
            for (int i = 0; i < 3; i++)
#pragma unroll
                for (int g = 0; g < 8; g++)
                    mma16816(acc[i][g], a[i], b[g][0], b[g][1]);
        }
        __syncthreads();
    }

    // -------- epilogue: accum -> SMEM [192][130], then max3 + arcface + store --------
    float* ep = (float*)smem_raw;
#pragma unroll
    for (int i = 0; i < 3; i++) {
        int row = wm0 + 16 * i + (lane >> 2);
#pragma unroll
        for (int g = 0; g < 8; g++) {
            int col = wn0 + 8 * g + 2 * (lane & 3);
            *(float2*)&ep[row * EPAD + col]       = make_float2(acc[i][g][0], acc[i][g][1]);
            *(float2*)&ep[(row + 8) * EPAD + col] = make_float2(acc[i][g][2], acc[i][g][3]);
        }
    }
    __syncthreads();

    const int cls  = tid & 63;           // local class; lanes consecutive -> coalesced
    const int bg   = tid >> 6;           // 0..3
    const int clsG = mtile * 64 + cls;
    if (clsG < NCLS) {
        const int r3 = 3 * cls;
#pragma unroll 4
        for (int i = 0; i < 32; i++) {
            int b = bg * 32 + i;
            float v0 = ep[r3 * EPAD + b];
            float v1 = ep[(r3 + 1) * EPAD + b];
            float v2 = ep[(r3 + 2) * EPAD + b];
            float m = fmaxf(v0, fmaxf(v1, v2));
            float v = m;
            if (g_labels[n0 + b] == clsG) {
                float mc = fminf(fmaxf(m, -1.0f + 1e-7f), 1.0f - 1e-7f);
                v = mc * COS_M - sqrtf(fmaxf(1.0f - mc * mc, 0.0f)) * SIN_M;
            }
            out[(size_t)(n0 + b) * NCLS + clsG] = S_SCALE * v;
        }
    }
}

// ---------------- Launch: two kernels total ----------------
extern "C" void kernel_launch(void* const* d_in, const int* in_sizes, int n_in,
                              void* d_out, int out_size) {
    (void)in_sizes; (void)n_in; (void)out_size;
    const float* emb = (const float*)d_in[0];
    const void*  lab = d_in[1];
    const float* wt  = (const float*)d_in[2];
    float* out = (float*)d_out;

    cudaFuncSetAttribute(arcface_gemm_kernel,
                         cudaFuncAttributeMaxDynamicSharedMemorySize, SMEM_DYN);

    // Launch 1: all prep (W-norm + E-norm + labels) in one full-GPU launch.
    prep_kernel<<<PREP_BLOCKS, 256>>>(wt, emb, lab);

    // Launch 2: GEMM (bit-exact R4 configuration, 544.5 us measured floor).
    dim3 grid(BATCH / NTB, MTILES);   // (8, 782), ntile fastest
    arcface_gemm_kernel<<<grid, 256, SMEM_DYN>>>(out);
}